// round 6
// baseline (speedup 1.0000x reference)
#include <cuda_runtime.h>
#include <cuda_bf16.h>

// CrossNetwork (DCN-v1): x_{l+1} = input * (x_l . w_l) + x_l + b_l, L=6.
//
// Closed form: x_l = alpha_l*input + y_l,  y_l = sum_{j<l} b_j,
//   p_l = input.w_l, q_l = y_l.w_l,  alpha_{l+1} = alpha_l*(1+p_l)+q_l,
//   out = alpha_L*input + y_L.
// One HBM read + one HBM write of [B,D] (128 MB).
//
// Round 4: fma.rn.f32x2 packed FMAs (halve FMA issue), double-buffered
// input prefetch issued BEFORE the smem preamble (hides preamble bubble),
// streaming stores (protect L2-resident input).

#define D 1024
#define L 6
#define NTHREADS 256
#define ROWS_PER_BLOCK 16   // 8 warps * 2 rows/warp
#define D4 (D / 4)          // 256 16-byte groups per row

typedef unsigned long long u64;

__device__ __forceinline__ u64 ffma2(u64 a, u64 b, u64 c) {
    u64 d;
    asm("fma.rn.f32x2 %0, %1, %2, %3;" : "=l"(d) : "l"(a), "l"(b), "l"(c));
    return d;
}
__device__ __forceinline__ u64 pack2(float lo, float hi) {
    u64 d;
    asm("mov.b64 %0, {%1, %2};" : "=l"(d) : "f"(lo), "f"(hi));
    return d;
}
__device__ __forceinline__ void unpack2(u64 v, float& lo, float& hi) {
    asm("mov.b64 {%0, %1}, %2;" : "=f"(lo), "=f"(hi) : "l"(v));
}

__global__ __launch_bounds__(NTHREADS, 3)
void crossnet_kernel(const float* __restrict__ input,
                     const float* __restrict__ Wg,
                     const float* __restrict__ bg,
                     float* __restrict__ out,
                     int B)
{
    __shared__ ulonglong2 w_s[L * D4];   // 24 KB: full W (f32x2-packed pairs)
    __shared__ ulonglong2 y_s[D4];       // 4 KB: y_L
    __shared__ float      q_s[L];

    const int tid  = threadIdx.x;
    const int lane = tid & 31;
    const int warp = tid >> 5;

    if (tid < L) q_s[tid] = 0.0f;

    // ---- rows for this warp (clamped; store-guarded) ----
    const int row0   = blockIdx.x * ROWS_PER_BLOCK + warp * 2;
    const bool v0    = (row0 < B);
    const bool v1    = (row0 + 1 < B);
    const int  rs0   = v0 ? row0 : 0;
    const int  rs1   = v1 ? row0 + 1 : rs0;

    const ulonglong2* p0 = reinterpret_cast<const ulonglong2*>(input) + (size_t)rs0 * D4;
    const ulonglong2* p1 = reinterpret_cast<const ulonglong2*>(input) + (size_t)rs1 * D4;

    // ---- issue first two input batches NOW (in flight during preamble) ----
    // buf[0..1] = row0 {k, k+1}, buf[2..3] = row1 {k, k+1}
    ulonglong2 bA[4], bB[4];
    bA[0] = p0[lane];        bA[1] = p0[lane + 32];
    bA[2] = p1[lane];        bA[3] = p1[lane + 32];
    bB[0] = p0[lane + 64];   bB[1] = p0[lane + 96];
    bB[2] = p1[lane + 64];   bB[3] = p1[lane + 96];

    // ---- preamble: W -> smem (overlaps the loads above) ----
    const ulonglong2* W2 = reinterpret_cast<const ulonglong2*>(Wg);
    const float4*     B4 = reinterpret_cast<const float4*>(bg);
#pragma unroll
    for (int i = 0; i < L; i++)
        w_s[i * D4 + tid] = W2[i * D4 + tid];
    __syncthreads();   // w_s + q_s zero visible

    // ---- y_L and q_l (redundant per block; cheap) ----
    {
        float4 y = make_float4(0.f, 0.f, 0.f, 0.f);
        float ql[L];
#pragma unroll
        for (int l = 0; l < L; l++) {
            ulonglong2 wp = w_s[l * D4 + tid];
            float wx, wy, wz, ww;
            unpack2(wp.x, wx, wy); unpack2(wp.y, wz, ww);
            float4 bb = B4[l * D4 + tid];
            ql[l] = y.x * wx + y.y * wy + y.z * wz + y.w * ww;
            y.x += bb.x; y.y += bb.y; y.z += bb.z; y.w += bb.w;
        }
        ulonglong2 yp; yp.x = pack2(y.x, y.y); yp.y = pack2(y.z, y.w);
        y_s[tid] = yp;
#pragma unroll
        for (int l = 0; l < L; l++) {
            float v = ql[l];
#pragma unroll
            for (int o = 16; o > 0; o >>= 1)
                v += __shfl_xor_sync(0xffffffffu, v, o);
            if (lane == 0) atomicAdd(&q_s[l], v);
        }
    }

    // ---- dot phase: packed f32x2 accumulators, double-buffered batches ----
    u64 acc0[L], acc1[L];
    const u64 z = 0ull;
#pragma unroll
    for (int l = 0; l < L; l++) { acc0[l] = z; acc1[l] = z; }

#define DOT_BATCH(buf, kbase)                                              \
    {                                                                      \
        _Pragma("unroll")                                                  \
        for (int j = 0; j < 2; j++) {                                      \
            const int ki = (kbase) + j;                                    \
            _Pragma("unroll")                                              \
            for (int l = 0; l < L; l++) {                                  \
                ulonglong2 w = w_s[l * D4 + lane + 32 * ki];               \
                acc0[l] = ffma2(buf[j].x,     w.x,                         \
                          ffma2(buf[j].y,     w.y, acc0[l]));              \
                acc1[l] = ffma2(buf[2 + j].x, w.x,                         \
                          ffma2(buf[2 + j].y, w.y, acc1[l]));              \
            }                                                              \
        }                                                                  \
    }

    DOT_BATCH(bA, 0)
    // refill A with k=4,5 while B computes
    bA[0] = p0[lane + 128]; bA[1] = p0[lane + 160];
    bA[2] = p1[lane + 128]; bA[3] = p1[lane + 160];
    DOT_BATCH(bB, 2)
    bB[0] = p0[lane + 192]; bB[1] = p0[lane + 224];
    bB[2] = p1[lane + 192]; bB[3] = p1[lane + 224];
    DOT_BATCH(bA, 4)
    DOT_BATCH(bB, 6)
#undef DOT_BATCH

    // ---- horizontal + warp reductions -> p_l per row ----
    float pr0[L], pr1[L];
#pragma unroll
    for (int l = 0; l < L; l++) {
        float lo, hi;
        unpack2(acc0[l], lo, hi); pr0[l] = lo + hi;
        unpack2(acc1[l], lo, hi); pr1[l] = lo + hi;
#pragma unroll
        for (int o = 16; o > 0; o >>= 1) {
            pr0[l] += __shfl_xor_sync(0xffffffffu, pr0[l], o);
            pr1[l] += __shfl_xor_sync(0xffffffffu, pr1[l], o);
        }
    }

    __syncthreads();   // q_s atomics + y_s visible

    // ---- scalar recurrence: alpha = alpha*(1+p) + q ----
    float a0 = 1.0f, a1 = 1.0f;
#pragma unroll
    for (int l = 0; l < L; l++) {
        float q = q_s[l];
        a0 = fmaf(a0, pr0[l], a0) + q;
        a1 = fmaf(a1, pr1[l], a1) + q;
    }
    const u64 a0p = pack2(a0, a0);
    const u64 a1p = pack2(a1, a1);

    // ---- epilogue: re-read input (L1/L2 hot), streaming stores ----
    ulonglong2* o0 = reinterpret_cast<ulonglong2*>(out) + (size_t)rs0 * D4;
    ulonglong2* o1 = reinterpret_cast<ulonglong2*>(out) + (size_t)rs1 * D4;
#pragma unroll
    for (int k = 0; k < 8; k++) {
        const int idx = lane + 32 * k;
        ulonglong2 y = y_s[idx];
        if (v0) {
            ulonglong2 i0 = p0[idx];
            ulonglong2 r0;
            r0.x = ffma2(a0p, i0.x, y.x);
            r0.y = ffma2(a0p, i0.y, y.y);
            asm volatile("st.global.cs.v2.b64 [%0], {%1, %2};"
                         :: "l"(o0 + idx), "l"(r0.x), "l"(r0.y) : "memory");
        }
        if (v1) {
            ulonglong2 i1 = p1[idx];
            ulonglong2 r1;
            r1.x = ffma2(a1p, i1.x, y.x);
            r1.y = ffma2(a1p, i1.y, y.y);
            asm volatile("st.global.cs.v2.b64 [%0], {%1, %2};"
                         :: "l"(o1 + idx), "l"(r1.x), "l"(r1.y) : "memory");
        }
    }
}

extern "C" void kernel_launch(void* const* d_in, const int* in_sizes, int n_in,
                              void* d_out, int out_size)
{
    const float* input = (const float*)d_in[0];
    const float* W     = (const float*)d_in[1];
    const float* b     = (const float*)d_in[2];
    float* out         = (float*)d_out;

    const int B    = in_sizes[0] / D;                           // 16384
    const int grid = (B + ROWS_PER_BLOCK - 1) / ROWS_PER_BLOCK; // 1024

    crossnet_kernel<<<grid, NTHREADS>>>(input, W, b, out, B);
}

// round 7
// speedup vs baseline: 1.2692x; 1.2692x over previous
#include <cuda_runtime.h>
#include <cuda_bf16.h>

// CrossNetwork (DCN-v1): x_{l+1} = input * (x_l . w_l) + x_l + b_l, L=6.
//
// Closed form: x_l = alpha_l*input + y_l,  y_l = sum_{j<l} b_j,
//   p_l = input.w_l, q_l = y_l.w_l,  alpha_{l+1} = alpha_l*(1+p_l)+q_l,
//   out = alpha_L*input + y_L.
// One HBM read + one HBM write of [B,D] (128 MB).
//
// Round 7: R2 compute core (register-resident input, scalar FMA, plain
// stores) + persistent CTAs with dynamic tile stealing. W/y/q preamble runs
// once per CTA (296x) instead of once per tile (1024x); no wave quantization.

#define D 1024
#define L 6
#define NTHREADS 256
#define ROWS_PER_BLOCK 16   // 8 warps * 2 rows/warp
#define D4 (D / 4)          // 256 float4 per row
#define GRID_CTAS 296       // 148 SMs * 2 resident CTAs

__device__ unsigned int g_tile_ctr = 0;
__device__ unsigned int g_done_ctr = 0;

__global__ __launch_bounds__(NTHREADS, 2)
void crossnet_kernel(const float* __restrict__ input,
                     const float* __restrict__ Wg,
                     const float* __restrict__ bg,
                     float* __restrict__ out,
                     int B, int ntiles)
{
    __shared__ float4 w_s[L * D4];   // 24 KB: full W
    __shared__ float4 y_s[D4];       // 4 KB: y_L = sum_l b_l
    __shared__ float  q_s[L];        // 6 scalars
    __shared__ unsigned int s_tile;

    const int tid  = threadIdx.x;
    const int lane = tid & 31;
    const int warp = tid >> 5;

    if (tid < L) q_s[tid] = 0.0f;

    // ---- one-time preamble: W -> smem ----
    const float4* W4 = reinterpret_cast<const float4*>(Wg);
    const float4* B4 = reinterpret_cast<const float4*>(bg);
#pragma unroll
    for (int i = 0; i < L; i++)
        w_s[i * D4 + tid] = W4[i * D4 + tid];
    __syncthreads();

    // ---- one-time: y_L and q_l ----
    {
        float4 y = make_float4(0.f, 0.f, 0.f, 0.f);
        float ql[L];
#pragma unroll
        for (int l = 0; l < L; l++) {
            float4 w  = w_s[l * D4 + tid];
            float4 bb = B4[l * D4 + tid];
            ql[l] = y.x * w.x + y.y * w.y + y.z * w.z + y.w * w.w;
            y.x += bb.x; y.y += bb.y; y.z += bb.z; y.w += bb.w;
        }
        y_s[tid] = y;
#pragma unroll
        for (int l = 0; l < L; l++) {
            float v = ql[l];
#pragma unroll
            for (int o = 16; o > 0; o >>= 1)
                v += __shfl_xor_sync(0xffffffffu, v, o);
            if (lane == 0) atomicAdd(&q_s[l], v);
        }
    }
    __syncthreads();   // w_s, y_s, q_s final

    // ---- persistent tile loop (dynamic work stealing) ----
    for (;;) {
        if (tid == 0) s_tile = atomicAdd(&g_tile_ctr, 1u);
        __syncthreads();
        const unsigned int tile = s_tile;
        __syncthreads();            // protect s_tile before next overwrite
        if (tile >= (unsigned int)ntiles) break;

        const int row0 = (int)tile * ROWS_PER_BLOCK + warp * 2;
        const bool r1ok = (row0 + 1 < B);
        if (row0 < B) {
            const float4* in0p = reinterpret_cast<const float4*>(input) + (size_t)row0 * D4;
            const float4* in1p = in0p + D4;

            // register-resident input (read HBM exactly once)
            float4 in0[8], in1[8];
#pragma unroll
            for (int k = 0; k < 8; k++) {
                in0[k] = in0p[lane + 32 * k];
                in1[k] = r1ok ? in1p[lane + 32 * k] : make_float4(0.f, 0.f, 0.f, 0.f);
            }

            float acc0[L], acc1[L];
#pragma unroll
            for (int l = 0; l < L; l++) { acc0[l] = 0.f; acc1[l] = 0.f; }

#pragma unroll
            for (int k = 0; k < 8; k++) {
#pragma unroll
                for (int l = 0; l < L; l++) {
                    float4 w = w_s[l * D4 + lane + 32 * k];
                    acc0[l] = fmaf(in0[k].x, w.x, acc0[l]);
                    acc0[l] = fmaf(in0[k].y, w.y, acc0[l]);
                    acc0[l] = fmaf(in0[k].z, w.z, acc0[l]);
                    acc0[l] = fmaf(in0[k].w, w.w, acc0[l]);
                    acc1[l] = fmaf(in1[k].x, w.x, acc1[l]);
                    acc1[l] = fmaf(in1[k].y, w.y, acc1[l]);
                    acc1[l] = fmaf(in1[k].z, w.z, acc1[l]);
                    acc1[l] = fmaf(in1[k].w, w.w, acc1[l]);
                }
            }

            // butterfly warp reductions -> every lane holds full p_l
#pragma unroll
            for (int l = 0; l < L; l++) {
#pragma unroll
                for (int o = 16; o > 0; o >>= 1) {
                    acc0[l] += __shfl_xor_sync(0xffffffffu, acc0[l], o);
                    acc1[l] += __shfl_xor_sync(0xffffffffu, acc1[l], o);
                }
            }

            // scalar recurrence: alpha = alpha*(1+p) + q
            float a0 = 1.0f, a1 = 1.0f;
#pragma unroll
            for (int l = 0; l < L; l++) {
                float q = q_s[l];
                a0 = fmaf(a0, acc0[l], a0) + q;
                a1 = fmaf(a1, acc1[l], a1) + q;
            }

            // epilogue: out = alpha * input + y_L (input from registers)
            float4* o0 = reinterpret_cast<float4*>(out) + (size_t)row0 * D4;
            float4* o1 = o0 + D4;
#pragma unroll
            for (int k = 0; k < 8; k++) {
                float4 y = y_s[lane + 32 * k];
                float4 r0;
                r0.x = fmaf(a0, in0[k].x, y.x);
                r0.y = fmaf(a0, in0[k].y, y.y);
                r0.z = fmaf(a0, in0[k].z, y.z);
                r0.w = fmaf(a0, in0[k].w, y.w);
                o0[lane + 32 * k] = r0;
                if (r1ok) {
                    float4 r1;
                    r1.x = fmaf(a1, in1[k].x, y.x);
                    r1.y = fmaf(a1, in1[k].y, y.y);
                    r1.z = fmaf(a1, in1[k].z, y.z);
                    r1.w = fmaf(a1, in1[k].w, y.w);
                    o1[lane + 32 * k] = r1;
                }
            }
        }
    }

    // ---- reset counters for next graph replay (last CTA out) ----
    __syncthreads();
    if (tid == 0) {
        __threadfence();
        unsigned int d = atomicAdd(&g_done_ctr, 1u);
        if (d == (unsigned int)gridDim.x - 1u) {
            atomicExch(&g_tile_ctr, 0u);
            atomicExch(&g_done_ctr, 0u);
        }
    }
}

extern "C" void kernel_launch(void* const* d_in, const int* in_sizes, int n_in,
                              void* d_out, int out_size)
{
    const float* input = (const float*)d_in[0];
    const float* W     = (const float*)d_in[1];
    const float* b     = (const float*)d_in[2];
    float* out         = (float*)d_out;

    const int B      = in_sizes[0] / D;                             // 16384
    const int ntiles = (B + ROWS_PER_BLOCK - 1) / ROWS_PER_BLOCK;   // 1024
    const int grid   = (ntiles < GRID_CTAS) ? ntiles : GRID_CTAS;   // 296

    crossnet_kernel<<<grid, NTHREADS>>>(input, W, b, out, B, ntiles);
}